// round 9
// baseline (speedup 1.0000x reference)
#include <cuda_runtime.h>
#include <cuda_pipeline.h>
#include <math.h>
#include <cstdint>

#define BATCH 16
#define NN    2048
#define KH    12
#define FD    128
#define OD    64

typedef unsigned int uint;

// ---------------- scratch (device global; no allocation) ----------------
__device__ float g_att[2 * NN * 36];

// ---------------------------------------------------------------------------
// Kernel A: attention matrices. One warp per (i, n); W@a inlined.
// ---------------------------------------------------------------------------
__global__ void __launch_bounds__(256) attn_scores_kernel(
    const float* __restrict__ h, const int* __restrict__ adj,
    const float* __restrict__ W, const float* __restrict__ a)
{
    __shared__ float wa1[FD], wa2[FD];
    const int t = threadIdx.x;
    const int i = blockIdx.x >> 8;               // 512 blocks: 256 per i

    if (t < FD) {
        float r1 = 0.f, r2 = 0.f;
        const float* wr = W + t * OD;
        const float* ap = a + i * 2 * OD;
        #pragma unroll 16
        for (int o = 0; o < OD; ++o) {
            const float w = wr[o];
            r1 = fmaf(w, ap[o], r1);
            r2 = fmaf(w, ap[OD + o], r2);
        }
        wa1[t] = r1; wa2[t] = r2;
    }
    __syncthreads();

    const int wid = t >> 5, l = t & 31;
    const int n = ((blockIdx.x & 255) << 3) + wid;

    const float4 w1 = *(const float4*)(wa1 + 4 * l);
    const float4 w2 = *(const float4*)(wa2 + 4 * l);

    float p1[6], p2[6];
    const float* hb = h + (((size_t)i * NN + n) * KH + i * 6) * FD + 4 * l;
    #pragma unroll
    for (int q = 0; q < 6; ++q) {
        const float4 hv = *(const float4*)(hb + q * FD);
        p1[q] = hv.x * w1.x + hv.y * w1.y + hv.z * w1.z + hv.w * w1.w;
        p2[q] = hv.x * w2.x + hv.y * w2.y + hv.z * w2.z + hv.w * w2.w;
    }
    #pragma unroll
    for (int off = 16; off > 0; off >>= 1) {
        #pragma unroll
        for (int q = 0; q < 6; ++q) {
            p1[q] += __shfl_xor_sync(0xffffffffu, p1[q], off);
            p2[q] += __shfl_xor_sync(0xffffffffu, p2[q], off);
        }
    }

    if (l < 6) {
        const int p = l;
        float e[6];
        float m = -1e30f;
        #pragma unroll
        for (int q = 0; q < 6; ++q) {
            float v = p1[p] + p2[q];
            v = v > 0.f ? v : 0.2f * v;
            if (adj[i * 36 + p * 6 + q] <= 0) v = -9.0e15f;
            e[q] = v;
            m = fmaxf(m, v);
        }
        float sum = 0.f;
        #pragma unroll
        for (int q = 0; q < 6; ++q) { e[q] = expf(e[q] - m); sum += e[q]; }
        const float inv = 1.f / sum;
        float* dst = g_att + ((size_t)i * NN + n) * 36 + p * 6;
        #pragma unroll
        for (int q = 0; q < 6; ++q) dst[q] = e[q] * inv;
    }
}

// ---------------------------------------------------------------------------
// Main kernel: cp.async-staged premix + bf16 hi/lo mma.sync GEMM.
// Tile = 4 n, padded to 16 rows each = 64 rows x K128 x N64.
// 8 tiles per CTA. 256 threads, 2 CTA/SM. Warp = 2 row-tiles x 16 cols.
// ---------------------------------------------------------------------------
#define SM_BHI  0                       // 16384 B
#define SM_BLO  16384
#define SM_AHI  32768                   // 64 rows x 256 B = 16384
#define SM_ALO  49152
#define SM_RAW  65536                   // 2 x 24576 (raw fp32, 4 n)
#define SM_TOT  114688                  // 112 KB

__device__ __forceinline__ void split2(float v0, float v1, uint& hp, uint& lp) {
    asm("cvt.rn.bf16x2.f32 %0, %1, %2;" : "=r"(hp) : "f"(v1), "f"(v0));
    const float h0 = __uint_as_float(hp << 16);
    const float h1 = __uint_as_float(hp & 0xffff0000u);
    asm("cvt.rn.bf16x2.f32 %0, %1, %2;" : "=r"(lp) : "f"(v1 - h1), "f"(v0 - h0));
}
__device__ __forceinline__ uint smem_u32(const void* p) {
    uint a;
    asm("{ .reg .u64 t; cvta.to.shared.u64 t, %1; cvt.u32.u64 %0, t; }"
        : "=r"(a) : "l"(p));
    return a;
}
__device__ __forceinline__ void ldsm4(uint* r, uint addr) {
    asm volatile("ldmatrix.sync.aligned.m8n8.x4.shared.b16 {%0,%1,%2,%3}, [%4];"
                 : "=r"(r[0]), "=r"(r[1]), "=r"(r[2]), "=r"(r[3]) : "r"(addr));
}
__device__ __forceinline__ void mma16816(float* d, const uint* a, uint b0, uint b1) {
    asm volatile("mma.sync.aligned.m16n8k16.row.col.f32.bf16.bf16.f32 "
                 "{%0,%1,%2,%3}, {%4,%5,%6,%7}, {%8,%9}, {%0,%1,%2,%3};"
                 : "+f"(d[0]), "+f"(d[1]), "+f"(d[2]), "+f"(d[3])
                 : "r"(a[0]), "r"(a[1]), "r"(a[2]), "r"(a[3]), "r"(b0), "r"(b1));
}

__global__ void __launch_bounds__(256, 2) gat_main_kernel(
    const float* __restrict__ h, const float* __restrict__ W,
    float* __restrict__ out)
{
    extern __shared__ char smem[];
    const uint sb = smem_u32(smem);
    const int t = threadIdx.x;
    const int w = t >> 5;
    const int lane = t & 31;
    const int b = blockIdx.y;
    const int nC = blockIdx.x * 32;       // 32 n per CTA (8 tiles of 4)

    // ---- Bs setup: W -> transposed bf16 hi/lo, XOR-swizzled ----
    {
        uint* BH = (uint*)(smem + SM_BHI);
        uint* BL = (uint*)(smem + SM_BLO);
        #pragma unroll
        for (int j = 0; j < 8; ++j) {
            const int ww = w * 8 + j;
            #pragma unroll
            for (int nh = 0; nh < 2; ++nh) {
                const int n = nh * 32 + lane;
                const float v0 = __ldg(W + (2 * ww) * OD + n);
                const float v1 = __ldg(W + (2 * ww + 1) * OD + n);
                uint hp, lp;
                split2(v0, v1, hp, lp);
                const int word = n * 64 + (ww ^ ((n & 7) << 2));
                BH[word] = hp;
                BL[word] = lp;
            }
        }
    }

    // ---- raw tile loader: 4 n = 1536 float4 contiguous ----
    auto load_raw = [&](int tile, int buf) {
        const float4* src = (const float4*)
            (h + (((size_t)b * NN + nC + tile * 4) * KH) * FD);
        float4* dst = (float4*)(smem + SM_RAW + buf * 24576);
        #pragma unroll
        for (int i2 = 0; i2 < 6; ++i2)
            __pipeline_memcpy_async(dst + t + i2 * 256, src + t + i2 * 256, 16);
    };

    // per-lane GEMM geometry: warp = (wc 16-col block, rw 2-rowtile block)
    const int wc    = w & 3;
    const int rw    = w >> 2;
    const int g     = lane >> 3;
    const int arow  = ((g & 1) << 3) + (lane & 7);
    const int acoff = g >> 1;
    const int as7   = arow & 7;
    const int nB0   = wc * 16 + (lane >> 2);
    const int nB1   = nB0 + 8;
    const int bxm0  = (nB0 & 7) << 2;
    const int bw0   = lane & 3;
    const uint* BH  = (const uint*)(smem + SM_BHI);
    const uint* BL  = (const uint*)(smem + SM_BLO);
    const int r0l   = lane >> 2;
    const int c0b   = wc * 16 + (lane & 3) * 2;

    // premix job: warp -> (nl = w>>1, gl = w&1)
    const int nlj = w >> 1;
    const int glj = w & 1;

    load_raw(0, 0);
    __pipeline_commit();

    for (int tl = 0; tl < 8; ++tl) {
        const int buf = tl & 1;
        const int n0 = nC + tl * 4;
        __pipeline_wait_prior(0);
        __syncthreads();                 // raw(tl) visible; A planes free

        // ---- premix: 1 job per warp, from raw smem ----
        {
            const int n = n0 + nlj;
            const float* rawb = (const float*)(smem + SM_RAW + buf * 24576)
                              + (nlj * 12 + glj * 6) * FD + lane * 4;
            float4 hq[6];
            #pragma unroll
            for (int q = 0; q < 6; ++q)
                hq[q] = *(const float4*)(rawb + q * FD);

            float at[36];
            const float4* ap4 =
                (const float4*)(g_att + ((size_t)glj * NN + n) * 36);
            #pragma unroll
            for (int k = 0; k < 9; ++k) {
                const float4 v = __ldg(ap4 + k);
                at[k * 4 + 0] = v.x; at[k * 4 + 1] = v.y;
                at[k * 4 + 2] = v.z; at[k * 4 + 3] = v.w;
            }

            const int rbase = nlj * 16 + glj * 6;     // padded rows
            const int c     = lane >> 1;
            const int half8 = (lane & 1) * 8;
            #pragma unroll
            for (int p = 0; p < 6; ++p) {
                float a0 = 0.f, a1 = 0.f, a2 = 0.f, a3 = 0.f;
                #pragma unroll
                for (int q = 0; q < 6; ++q) {
                    const float aq = at[p * 6 + q];
                    a0 = fmaf(aq, hq[q].x, a0);
                    a1 = fmaf(aq, hq[q].y, a1);
                    a2 = fmaf(aq, hq[q].z, a2);
                    a3 = fmaf(aq, hq[q].w, a3);
                }
                uint h0, l0, h1, l1;
                split2(a0, a1, h0, l0);
                split2(a2, a3, h1, l1);
                const int r = rbase + p;
                const uint off = (uint)(r * 256 + ((c ^ (r & 7)) << 4) + half8);
                *(uint2*)(smem + SM_AHI + off) = make_uint2(h0, h1);
                *(uint2*)(smem + SM_ALO + off) = make_uint2(l0, l1);
            }
        }
        __syncthreads();

        // prefetch next raw tile under the GEMM
        if (tl < 7) { load_raw(tl + 1, buf ^ 1); __pipeline_commit(); }

        // ---- GEMM: warp -> 2 row-tiles (rw*2..+1), 16 cols ----
        float d[2][2][4];
        #pragma unroll
        for (int rti = 0; rti < 2; ++rti)
            #pragma unroll
            for (int ct = 0; ct < 2; ++ct)
                #pragma unroll
                for (int e = 0; e < 4; ++e) d[rti][ct][e] = 0.f;

        #pragma unroll 2
        for (int s = 0; s < 8; ++s) {
            const int i0 = (bw0 + 8 * s) ^ bxm0;
            const int i1 = (bw0 + 4 + 8 * s) ^ bxm0;
            const uint bh0[2] = { BH[nB0 * 64 + i0], BH[nB1 * 64 + i0] };
            const uint bh1[2] = { BH[nB0 * 64 + i1], BH[nB1 * 64 + i1] };
            const uint bl0[2] = { BL[nB0 * 64 + i0], BL[nB1 * 64 + i0] };
            const uint bl1[2] = { BL[nB0 * 64 + i1], BL[nB1 * 64 + i1] };
            #pragma unroll
            for (int rti = 0; rti < 2; ++rti) {
                const int rt = rw * 2 + rti;
                const uint ra = (uint)((rt * 16 + arow) * 256
                                       + (((2 * s + acoff) ^ as7) << 4));
                uint ah[4], al[4];
                ldsm4(ah, sb + SM_AHI + ra);
                ldsm4(al, sb + SM_ALO + ra);
                #pragma unroll
                for (int ct = 0; ct < 2; ++ct) {
                    mma16816(d[rti][ct], ah, bh0[ct], bh1[ct]);
                    mma16816(d[rti][ct], ah, bl0[ct], bl1[ct]);
                    mma16816(d[rti][ct], al, bh0[ct], bh1[ct]);
                }
            }
        }

        // ---- epilogue: ELU + store (skip padding rows kh >= 12) ----
        #pragma unroll
        for (int rti = 0; rti < 2; ++rti) {
            const int rt = rw * 2 + rti;         // = local n
            #pragma unroll
            for (int hf = 0; hf < 2; ++hf) {
                const int kh = r0l + hf * 8;     // 0..15
                if (kh < 12) {
                    float* ob = out + (((size_t)b * NN + n0 + rt) * KH + kh) * OD;
                    #pragma unroll
                    for (int ct = 0; ct < 2; ++ct) {
                        const float e0r = d[rti][ct][hf * 2];
                        const float e1r = d[rti][ct][hf * 2 + 1];
                        float2 o;
                        o.x = e0r > 0.f ? e0r : expm1f(e0r);
                        o.y = e1r > 0.f ? e1r : expm1f(e1r);
                        *(float2*)(ob + c0b + ct * 8) = o;
                    }
                }
            }
        }
        // A-plane reuse hazard handled by the sync at top of next iter
    }
}

// ---------------------------------------------------------------------------
extern "C" void kernel_launch(void* const* d_in, const int* in_sizes, int n_in,
                              void* d_out, int out_size)
{
    (void)in_sizes; (void)n_in; (void)out_size;
    const float* h   = (const float*)d_in[0];
    const int*   adj = (const int*)d_in[1];
    const float* W   = (const float*)d_in[2];
    const float* a   = (const float*)d_in[3];
    float* out = (float*)d_out;

    attn_scores_kernel<<<512, 256>>>(h, adj, W, a);

    cudaFuncSetAttribute(gat_main_kernel,
                         cudaFuncAttributeMaxDynamicSharedMemorySize, SM_TOT);
    gat_main_kernel<<<dim3(64, BATCH), 256, SM_TOT>>>(h, W, out);
}

// round 10
// speedup vs baseline: 1.2001x; 1.2001x over previous
#include <cuda_runtime.h>
#include <math.h>
#include <cstdint>

#define BATCH 16
#define NN    2048
#define KH    12
#define FD    128
#define OD    64

typedef unsigned int uint;

// ---------------- scratch (device global; no allocation) ----------------
__device__ float g_att[2 * NN * 36];

// ---------------------------------------------------------------------------
// Kernel A: attention matrices. One warp per (i, n); W@a inlined.
// ---------------------------------------------------------------------------
__global__ void __launch_bounds__(256) attn_scores_kernel(
    const float* __restrict__ h, const int* __restrict__ adj,
    const float* __restrict__ W, const float* __restrict__ a)
{
    __shared__ float wa1[FD], wa2[FD];
    const int t = threadIdx.x;
    const int i = blockIdx.x >> 8;               // 512 blocks: 256 per i

    if (t < FD) {
        float r1 = 0.f, r2 = 0.f;
        const float* wr = W + t * OD;
        const float* ap = a + i * 2 * OD;
        #pragma unroll 16
        for (int o = 0; o < OD; ++o) {
            const float w = wr[o];
            r1 = fmaf(w, ap[o], r1);
            r2 = fmaf(w, ap[OD + o], r2);
        }
        wa1[t] = r1; wa2[t] = r2;
    }
    __syncthreads();

    const int wid = t >> 5, l = t & 31;
    const int n = ((blockIdx.x & 255) << 3) + wid;

    const float4 w1 = *(const float4*)(wa1 + 4 * l);
    const float4 w2 = *(const float4*)(wa2 + 4 * l);

    float p1[6], p2[6];
    const float* hb = h + (((size_t)i * NN + n) * KH + i * 6) * FD + 4 * l;
    #pragma unroll
    for (int q = 0; q < 6; ++q) {
        const float4 hv = *(const float4*)(hb + q * FD);
        p1[q] = hv.x * w1.x + hv.y * w1.y + hv.z * w1.z + hv.w * w1.w;
        p2[q] = hv.x * w2.x + hv.y * w2.y + hv.z * w2.z + hv.w * w2.w;
    }
    #pragma unroll
    for (int off = 16; off > 0; off >>= 1) {
        #pragma unroll
        for (int q = 0; q < 6; ++q) {
            p1[q] += __shfl_xor_sync(0xffffffffu, p1[q], off);
            p2[q] += __shfl_xor_sync(0xffffffffu, p2[q], off);
        }
    }

    if (l < 6) {
        const int p = l;
        float e[6];
        float m = -1e30f;
        #pragma unroll
        for (int q = 0; q < 6; ++q) {
            float v = p1[p] + p2[q];
            v = v > 0.f ? v : 0.2f * v;
            if (adj[i * 36 + p * 6 + q] <= 0) v = -9.0e15f;
            e[q] = v;
            m = fmaxf(m, v);
        }
        float sum = 0.f;
        #pragma unroll
        for (int q = 0; q < 6; ++q) { e[q] = expf(e[q] - m); sum += e[q]; }
        const float inv = 1.f / sum;
        float* dst = g_att + ((size_t)i * NN + n) * 36 + p * 6;
        #pragma unroll
        for (int q = 0; q < 6; ++q) dst[q] = e[q] * inv;
    }
}

// ---------------------------------------------------------------------------
// Main kernel: register-pipelined premix + bf16 hi/lo mma.sync GEMM.
// Tile = 8 n = 96 rows x K128 x N64. 4 tiles per CTA. 256 threads, 2 CTA/SM.
// Warp = 3 row-tiles x 16 cols. Next tile's h LDGs issued BEFORE the GEMM so
// DRAM latency hides under the MMAs (premix consumes landed registers).
// ---------------------------------------------------------------------------
#define SM_BHI  0                       // 16384 B
#define SM_BLO  16384
#define SM_AHI  32768                   // 96 rows x 256 B = 24576
#define SM_ALO  57344
#define SM_TOT  81920

__device__ __forceinline__ void split2(float v0, float v1, uint& hp, uint& lp) {
    asm("cvt.rn.bf16x2.f32 %0, %1, %2;" : "=r"(hp) : "f"(v1), "f"(v0));
    const float h0 = __uint_as_float(hp << 16);
    const float h1 = __uint_as_float(hp & 0xffff0000u);
    asm("cvt.rn.bf16x2.f32 %0, %1, %2;" : "=r"(lp) : "f"(v1 - h1), "f"(v0 - h0));
}
__device__ __forceinline__ uint smem_u32(const void* p) {
    uint a;
    asm("{ .reg .u64 t; cvta.to.shared.u64 t, %1; cvt.u32.u64 %0, t; }"
        : "=r"(a) : "l"(p));
    return a;
}
__device__ __forceinline__ void ldsm4(uint* r, uint addr) {
    asm volatile("ldmatrix.sync.aligned.m8n8.x4.shared.b16 {%0,%1,%2,%3}, [%4];"
                 : "=r"(r[0]), "=r"(r[1]), "=r"(r[2]), "=r"(r[3]) : "r"(addr));
}
__device__ __forceinline__ void mma16816(float* d, const uint* a, uint b0, uint b1) {
    asm volatile("mma.sync.aligned.m16n8k16.row.col.f32.bf16.bf16.f32 "
                 "{%0,%1,%2,%3}, {%4,%5,%6,%7}, {%8,%9}, {%0,%1,%2,%3};"
                 : "+f"(d[0]), "+f"(d[1]), "+f"(d[2]), "+f"(d[3])
                 : "r"(a[0]), "r"(a[1]), "r"(a[2]), "r"(a[3]), "r"(b0), "r"(b1));
}

__global__ void __launch_bounds__(256, 2) gat_main_kernel(
    const float* __restrict__ h, const float* __restrict__ W,
    float* __restrict__ out)
{
    extern __shared__ char smem[];
    const uint sb = smem_u32(smem);
    const int t = threadIdx.x;
    const int w = t >> 5;
    const int lane = t & 31;
    const int b = blockIdx.y;

    // ---- Bs setup: W -> transposed bf16 hi/lo, XOR-swizzled ----
    {
        uint* BH = (uint*)(smem + SM_BHI);
        uint* BL = (uint*)(smem + SM_BLO);
        #pragma unroll
        for (int j = 0; j < 8; ++j) {
            const int ww = w * 8 + j;
            #pragma unroll
            for (int nh = 0; nh < 2; ++nh) {
                const int n = nh * 32 + lane;
                const float v0 = __ldg(W + (2 * ww) * OD + n);
                const float v1 = __ldg(W + (2 * ww + 1) * OD + n);
                uint hp, lp;
                split2(v0, v1, hp, lp);
                const int word = n * 64 + (ww ^ ((n & 7) << 2));
                BH[word] = hp;
                BL[word] = lp;
            }
        }
    }

    // per-lane GEMM geometry (identical to verified R8 kernel)
    const int wc    = w & 3;
    const int rw    = w >> 2;
    const int g     = lane >> 3;
    const int arow  = ((g & 1) << 3) + (lane & 7);
    const int acoff = g >> 1;
    const int as7   = arow & 7;
    const int nB0   = wc * 16 + (lane >> 2);
    const int nB1   = nB0 + 8;
    const int bxm0  = (nB0 & 7) << 2;
    const int bw0   = lane & 3;
    const uint* BH  = (const uint*)(smem + SM_BHI);
    const uint* BL  = (const uint*)(smem + SM_BLO);
    const int r0l   = lane >> 2;
    const int c0b   = wc * 16 + (lane & 3) * 2;

    // premix jobs: job A = (nlA = w>>1, gl), job B = (nlA+4, same gl)
    const int nlA = w >> 1;
    const int gl  = w & 1;

    const int tile0 = blockIdx.x * 4;

    // issue h LDGs for a tile into register sets
    float4 hqA[6], hqB[6];
    auto issue_hq = [&](int n0) {
        const float* b1 = h + (((size_t)b * NN + n0 + nlA) * KH + gl * 6) * FD
                            + lane * 4;
        const float* b2 = h + (((size_t)b * NN + n0 + nlA + 4) * KH + gl * 6) * FD
                            + lane * 4;
        #pragma unroll
        for (int q = 0; q < 6; ++q) {
            hqA[q] = *(const float4*)(b1 + q * FD);
            hqB[q] = *(const float4*)(b2 + q * FD);
        }
    };

    // premix compute: mix 6 rows by att, bf16-split, store swizzled A planes
    const int cch   = lane >> 1;
    const int half8 = (lane & 1) * 8;
    auto premix_job = [&](const float4* hq, int n, int nl) {
        float at[36];
        const float4* ap4 = (const float4*)(g_att + ((size_t)gl * NN + n) * 36);
        #pragma unroll
        for (int k = 0; k < 9; ++k) {
            const float4 v = __ldg(ap4 + k);
            at[k * 4 + 0] = v.x; at[k * 4 + 1] = v.y;
            at[k * 4 + 2] = v.z; at[k * 4 + 3] = v.w;
        }
        const int rbase = nl * 12 + gl * 6;
        #pragma unroll
        for (int p = 0; p < 6; ++p) {
            float a0 = 0.f, a1 = 0.f, a2 = 0.f, a3 = 0.f;
            #pragma unroll
            for (int q = 0; q < 6; ++q) {
                const float aq = at[p * 6 + q];
                a0 = fmaf(aq, hq[q].x, a0);
                a1 = fmaf(aq, hq[q].y, a1);
                a2 = fmaf(aq, hq[q].z, a2);
                a3 = fmaf(aq, hq[q].w, a3);
            }
            uint h0, l0, h1, l1;
            split2(a0, a1, h0, l0);
            split2(a2, a3, h1, l1);
            const int r = rbase + p;
            const uint off = (uint)(r * 256 + ((cch ^ (r & 7)) << 4) + half8);
            *(uint2*)(smem + SM_AHI + off) = make_uint2(h0, h1);
            *(uint2*)(smem + SM_ALO + off) = make_uint2(l0, l1);
        }
    };

    issue_hq(tile0 * 8);      // preload tile 0

    for (int tl = 0; tl < 4; ++tl) {
        const int n0 = (tile0 + tl) * 8;

        // ---- premix from landed registers ----
        premix_job(hqA, n0 + nlA, nlA);
        premix_job(hqB, n0 + nlA + 4, nlA + 4);
        __syncthreads();

        // ---- prefetch next tile's h into registers (hides under GEMM) ----
        if (tl < 3) issue_hq(n0 + 8);

        // ---- GEMM: warp -> rows rw*48..+47 (3 m16 tiles), 16 cols ----
        float d[3][2][4];
        #pragma unroll
        for (int rti = 0; rti < 3; ++rti)
            #pragma unroll
            for (int ct = 0; ct < 2; ++ct)
                #pragma unroll
                for (int e = 0; e < 4; ++e) d[rti][ct][e] = 0.f;

        #pragma unroll 2
        for (int s = 0; s < 8; ++s) {
            const int i0 = (bw0 + 8 * s) ^ bxm0;
            const int i1 = (bw0 + 4 + 8 * s) ^ bxm0;
            const uint bh0[2] = { BH[nB0 * 64 + i0], BH[nB1 * 64 + i0] };
            const uint bh1[2] = { BH[nB0 * 64 + i1], BH[nB1 * 64 + i1] };
            const uint bl0[2] = { BL[nB0 * 64 + i0], BL[nB1 * 64 + i0] };
            const uint bl1[2] = { BL[nB0 * 64 + i1], BL[nB1 * 64 + i1] };
            #pragma unroll
            for (int rti = 0; rti < 3; ++rti) {
                const int rt = rw * 3 + rti;
                const uint ra = (uint)((rt * 16 + arow) * 256
                                       + (((2 * s + acoff) ^ as7) << 4));
                uint ah[4], al[4];
                ldsm4(ah, sb + SM_AHI + ra);
                ldsm4(al, sb + SM_ALO + ra);
                #pragma unroll
                for (int ct = 0; ct < 2; ++ct) {
                    mma16816(d[rti][ct], ah, bh0[ct], bh1[ct]);
                    mma16816(d[rti][ct], ah, bl0[ct], bl1[ct]);
                    mma16816(d[rti][ct], al, bh0[ct], bh1[ct]);
                }
            }
        }

        // ---- epilogue: ELU + store ----
        #pragma unroll
        for (int rti = 0; rti < 3; ++rti) {
            #pragma unroll
            for (int hf = 0; hf < 2; ++hf) {
                const int row = (rw * 3 + rti) * 16 + r0l + hf * 8;
                const int nl  = row / 12;
                const int kh  = row - nl * 12;
                float* ob = out + (((size_t)b * NN + n0 + nl) * KH + kh) * OD;
                #pragma unroll
                for (int ct = 0; ct < 2; ++ct) {
                    const float e0r = d[rti][ct][hf * 2];
                    const float e1r = d[rti][ct][hf * 2 + 1];
                    float2 o;
                    o.x = e0r > 0.f ? e0r : expm1f(e0r);
                    o.y = e1r > 0.f ? e1r : expm1f(e1r);
                    *(float2*)(ob + c0b + ct * 8) = o;
                }
            }
        }
        __syncthreads();   // A planes reusable next tile
    }
}

// ---------------------------------------------------------------------------
extern "C" void kernel_launch(void* const* d_in, const int* in_sizes, int n_in,
                              void* d_out, int out_size)
{
    (void)in_sizes; (void)n_in; (void)out_size;
    const float* h   = (const float*)d_in[0];
    const int*   adj = (const int*)d_in[1];
    const float* W   = (const float*)d_in[2];
    const float* a   = (const float*)d_in[3];
    float* out = (float*)d_out;

    attn_scores_kernel<<<512, 256>>>(h, adj, W, a);

    cudaFuncSetAttribute(gat_main_kernel,
                         cudaFuncAttributeMaxDynamicSharedMemorySize, SM_TOT);
    gat_main_kernel<<<dim3(64, BATCH), 256, SM_TOT>>>(h, W, out);
}